// round 16
// baseline (speedup 1.0000x reference)
#include <cuda_runtime.h>

#define NB    4
#define NP    4096
#define KP    11                 // K+1 including self
#define NFEAT 66
#define GC    16                 // grid cells per axis
#define NCELL (GC*GC*GC)         // 4096
#define XMIN  (-4.5f)
#define XMAX  (4.5f)
#define HCELL (9.0f/(float)GC)   // 0.5625
#define IHINV ((float)GC/9.0f)
#define WPQ   8                  // warps (queries) per search block

typedef unsigned long long ull;
#define SENT 0xFFFFFFFFFFFFFFFFull
#define FULLM 0xFFFFFFFFu

__device__ float  g_Weff[6 * NFEAT];
__device__ float  g_beff[6];
__device__ float4 g_spos[NB][NP];          // x,y,z, idx-as-float-bits
__device__ int    g_cs[NB][NCELL + 1];

__device__ __forceinline__ int cell1(float v) {
    int c = (int)(__fmul_rn(__fsub_rn(v, XMIN), IHINV));
    return min(GC - 1, max(0, c));
}
__device__ __forceinline__ unsigned f2ord(float f) {
    unsigned u = __float_as_uint(f);
    return u ^ (((int)u >> 31) | 0x80000000u);
}

// ---------------------------------------------------------------------------
// Fused prep: blocks 0..NB-1 build the per-batch grid; block NB folds weights.
#define BT 512
__global__ void __launch_bounds__(BT)
prep_kernel(const float* __restrict__ pos,
            const float* __restrict__ W1, const float* __restrict__ b1,
            const float* __restrict__ W2, const float* __restrict__ b2,
            const float* __restrict__ W3, const float* __restrict__ b3) {
    __shared__ int hist[NCELL];          // counts -> starts -> cursors
    __shared__ int wsum[BT / 32];
    const int t = threadIdx.x;

    if (blockIdx.x == NB) {
        // ---- fold weights: Weff = W3@W2@W1, beff = W3@(W2@b1+b2)+b3 ----
        __shared__ float sW1[32 * NFEAT];
        __shared__ float sW2[16 * 32];
        __shared__ float sW3[6 * 16];
        __shared__ float sb1[32], sb2[16];
        __shared__ float W32[6 * 32];
        __shared__ float bh[16];
        for (int i = t; i < 32 * NFEAT; i += BT) sW1[i] = W1[i];
        if (t < 512) sW2[t] = W2[t];
        if (t < 96) sW3[t] = W3[t];
        if (t < 32) sb1[t] = b1[t];
        if (t < 16) sb2[t] = b2[t];
        __syncthreads();
        if (t < 192) {
            int c = t >> 5, jj = t & 31;
            float s = 0.f;
            #pragma unroll
            for (int i = 0; i < 16; ++i) s += sW3[c * 16 + i] * sW2[i * 32 + jj];
            W32[c * 32 + jj] = s;
        } else if (t < 208) {
            int i = t - 192;
            float s = sb2[i];
            #pragma unroll
            for (int j = 0; j < 32; ++j) s += sW2[i * 32 + j] * sb1[j];
            bh[i] = s;
        }
        __syncthreads();
        if (t < 396) {
            int c = t / NFEAT, f = t % NFEAT;
            float s = 0.f;
            #pragma unroll
            for (int jj = 0; jj < 32; ++jj) s += W32[c * 32 + jj] * sW1[jj * NFEAT + f];
            g_Weff[c * NFEAT + f] = s;
        } else if (t < 402) {
            int c = t - 396;
            float s = b3[c];
            #pragma unroll
            for (int i = 0; i < 16; ++i) s += sW3[c * 16 + i] * bh[i];
            g_beff[c] = s;
        }
        return;
    }

    // ---- grid build for batch b ----
    const int b = blockIdx.x;
    const int lane = t & 31, w = t >> 5;
    const float* pb = pos + (size_t)b * NP * 3;

    for (int i = t; i < NCELL; i += BT) hist[i] = 0;
    __syncthreads();

    int myc[NP / BT];
    #pragma unroll
    for (int k = 0; k < NP / BT; ++k) {
        int i = t + k * BT;
        float x = pb[3 * i + 0], y = pb[3 * i + 1], z = pb[3 * i + 2];
        int c = (cell1(z) * GC + cell1(y)) * GC + cell1(x);
        myc[k] = c;
        atomicAdd(&hist[c], 1);
    }
    __syncthreads();

    // exclusive scan of NCELL counts: NCELL/BT cells/thread + shuffle scan
    {
        const int base = t * (NCELL / BT);
        int ex[NCELL / BT]; int s = 0;
        #pragma unroll
        for (int k = 0; k < NCELL / BT; ++k) { ex[k] = s; s += hist[base + k]; }
        int v = s;
        #pragma unroll
        for (int off = 1; off < 32; off <<= 1) {
            int u = __shfl_up_sync(FULLM, v, off);
            if (lane >= off) v += u;
        }
        if (lane == 31) wsum[w] = v;
        __syncthreads();
        if (w == 0) {
            int wv = (lane < BT / 32) ? wsum[lane] : 0;
            #pragma unroll
            for (int off = 1; off < 32; off <<= 1) {
                int u = __shfl_up_sync(FULLM, wv, off);
                if (lane >= off) wv += u;
            }
            if (lane < BT / 32) wsum[lane] = wv;
        }
        __syncthreads();
        int woff = (w == 0) ? 0 : wsum[w - 1];
        int tbase = woff + (v - s);
        __syncthreads();                 // reads of hist done before overwrite
        #pragma unroll
        for (int k = 0; k < NCELL / BT; ++k) {
            int st = tbase + ex[k];
            g_cs[b][base + k] = st;
            hist[base + k] = st;         // becomes scatter cursor
        }
        if (t == 0) g_cs[b][NCELL] = NP;
    }
    __syncthreads();

    #pragma unroll
    for (int k = 0; k < NP / BT; ++k) {
        int i = t + k * BT;
        float x = pb[3 * i + 0], y = pb[3 * i + 1], z = pb[3 * i + 2];
        int off = atomicAdd(&hist[myc[k]], 1);
        g_spos[b][off] = make_float4(x, y, z, __int_as_float(i));
    }
}

// ---------------------------------------------------------------------------
// Search: one warp per query. Per-lane sorted top-11 on u64 keys
// (ord(d2)<<32 | orig_idx). Phase order: own cell -> 6 face cells (plus) ->
// exact plus-bound break -> rest of 3x3x3 -> box-face break -> ring walk.
// All break tests use the capped-count REDUX (proven exact). Final 11-round
// REDUX min-extract. d2 arithmetic bit-pinned to the reference's lowering.
__global__ void __launch_bounds__(WPQ * 32)
search_kernel(const float* __restrict__ pos,
              const float* __restrict__ vel,
              const float* __restrict__ init_cfg,
              float* __restrict__ out) {
    __shared__ float Wsh[6 * NFEAT];
    __shared__ float bsh[8];
    const int tid = threadIdx.x;
    for (int i = tid; i < 6 * NFEAT; i += WPQ * 32) Wsh[i] = g_Weff[i];
    if (tid < 6) bsh[tid] = g_beff[tid];
    __syncthreads();

    const int wid  = tid >> 5;
    const int lane = tid & 31;
    const int b    = blockIdx.y;
    const int s_q  = blockIdx.x * WPQ + wid;      // sorted query index

    const float4 q = g_spos[b][s_q];
    const int    n = __float_as_int(q.w);         // original query index
    const float qsq = __fadd_rn(__fadd_rn(__fmul_rn(q.x, q.x), __fmul_rn(q.y, q.y)),
                                __fmul_rn(q.z, q.z));
    const float qcx = fminf(fmaxf(q.x, XMIN), XMAX);
    const float qcy = fminf(fmaxf(q.y, XMIN), XMAX);
    const float qcz = fminf(fmaxf(q.z, XMIN), XMAX);
    const int cx = cell1(q.x), cy = cell1(q.y), cz = cell1(q.z);
    const int*    csb = g_cs[b];
    const float4* sp  = g_spos[b];

    ull hk[KP];
    #pragma unroll
    for (int s = 0; s < KP; ++s) hk[s] = SENT;

    auto scan_range = [&](int a, int e) {
        for (int i = a + lane; i < e; i += 32) {
            float4 p = __ldg(&sp[i]);
            float psq = __fadd_rn(__fadd_rn(__fmul_rn(p.x, p.x), __fmul_rn(p.y, p.y)),
                                  __fmul_rn(p.z, p.z));
            float dot = __fmul_rn(q.x, p.x);
            dot = __fmaf_rn(q.y, p.y, dot);
            dot = __fmaf_rn(q.z, p.z, dot);
            float S  = __fadd_rn(qsq, psq);
            float d2 = __fsub_rn(S, __fmul_rn(2.0f, dot));
            ull key = ((ull)f2ord(d2) << 32) | (unsigned)__float_as_int(p.w);
            if (key < hk[KP - 1]) {
                hk[KP - 1] = key;
                #pragma unroll
                for (int s = KP - 1; s > 0; --s) {
                    if (hk[s] < hk[s - 1]) { ull t2 = hk[s - 1]; hk[s - 1] = hk[s]; hk[s] = t2; }
                    else break;
                }
            }
        }
    };

    // capped-count exact test: >= KP union keys strictly below bnd2?
    auto count_break = [&](float bnd2) -> bool {
        if (!(bnd2 > 1e-12f)) return false;
        unsigned bkey = f2ord(__fmul_rn(0.998f, bnd2));
        unsigned cnt = 0;
        #pragma unroll
        for (int s = 0; s < KP; ++s) cnt += ((unsigned)(hk[s] >> 32) < bkey) ? 1u : 0u;
        return __reduce_add_sync(FULLM, cnt) >= KP;
    };

    // per-axis distance from (clamped) q to the nearest own-cell face that has
    // grid cells beyond it (no cells beyond -> +inf, nothing unscanned there)
    float ax = 1e30f, ay = 1e30f, az = 1e30f;
    if (cx > 0)      ax = fminf(ax, qcx - (XMIN + (float)cx * HCELL));
    if (cx < GC - 1) ax = fminf(ax, (XMIN + (float)(cx + 1) * HCELL) - qcx);
    if (cy > 0)      ay = fminf(ay, qcy - (XMIN + (float)cy * HCELL));
    if (cy < GC - 1) ay = fminf(ay, (XMIN + (float)(cy + 1) * HCELL) - qcy);
    if (cz > 0)      az = fminf(az, qcz - (XMIN + (float)cz * HCELL));
    if (cz < GC - 1) az = fminf(az, (XMIN + (float)(cz + 1) * HCELL) - qcz);
    ax = fmaxf(ax, 0.f); ay = fmaxf(ay, 0.f); az = fmaxf(az, 0.f);

    bool done = false;

    // phase 1: own cell + 6 face-adjacent cells (the "plus")
    {
        int rb = (cz * GC + cy) * GC;
        scan_range(__ldg(&csb[rb + cx]), __ldg(&csb[rb + cx + 1]));          // own
        if (cx > 0)      scan_range(__ldg(&csb[rb + cx - 1]), __ldg(&csb[rb + cx]));
        if (cx < GC - 1) scan_range(__ldg(&csb[rb + cx + 1]), __ldg(&csb[rb + cx + 2]));
        if (cy > 0)      { int r2 = (cz * GC + cy - 1) * GC; scan_range(__ldg(&csb[r2 + cx]), __ldg(&csb[r2 + cx + 1])); }
        if (cy < GC - 1) { int r2 = (cz * GC + cy + 1) * GC; scan_range(__ldg(&csb[r2 + cx]), __ldg(&csb[r2 + cx + 1])); }
        if (cz > 0)      { int r2 = ((cz - 1) * GC + cy) * GC; scan_range(__ldg(&csb[r2 + cx]), __ldg(&csb[r2 + cx + 1])); }
        if (cz < GC - 1) { int r2 = ((cz + 1) * GC + cy) * GC; scan_range(__ldg(&csb[r2 + cx]), __ldg(&csb[r2 + cx + 1])); }

        // exact bound on unscanned space: >=2 axes off => sqrt(pair of axis
        // dists); >=2 cells off on one axis => min-axis + H. (clamped-space
        // lower bound; clamping is 1-Lipschitz so true dists only larger)
        float p1 = ax * ax + ay * ay;
        float p2 = ax * ax + az * az;
        float p3 = ay * ay + az * az;
        float am = fminf(ax, fminf(ay, az)) + HCELL;
        float bnd2 = fminf(fminf(p1, p2), fminf(p3, am * am));
        done = count_break(bnd2);
    }

    // phase 2: rest of the 3x3x3 box (edges + corners of ring 1)
    if (!done) {
        int xlo = max(cx - 1, 0), xhi = min(cx + 1, GC - 1);
        #pragma unroll
        for (int dz = -1; dz <= 1; ++dz) {
            int z = cz + dz; if ((unsigned)z >= GC) continue;
            #pragma unroll
            for (int dy = -1; dy <= 1; ++dy) {
                int y = cy + dy; if ((unsigned)y >= GC) continue;
                int rb = (z * GC + y) * GC;
                if (dz == 0 && dy == 0) continue;          // center row fully done
                if (dz == 0 || dy == 0) {                  // edge rows: skip x=cx
                    if (cx > 0)      scan_range(__ldg(&csb[rb + cx - 1]), __ldg(&csb[rb + cx]));
                    if (cx < GC - 1) scan_range(__ldg(&csb[rb + cx + 1]), __ldg(&csb[rb + cx + 2]));
                } else {                                   // corner rows: full
                    scan_range(__ldg(&csb[rb + xlo]), __ldg(&csb[rb + xhi + 1]));
                }
            }
        }
        // box-face bound after full ring 1 (R=1): faces one cell out
        float bx = fminf(ax + HCELL, 1e30f);
        // recompute exact per-axis face distances for the R=1 box
        float fx = 1e30f, fy = 1e30f, fz = 1e30f;
        if (cx - 1 > 0)      fx = fminf(fx, qcx - (XMIN + (float)(cx - 1) * HCELL));
        if (cx + 1 < GC - 1) fx = fminf(fx, (XMIN + (float)(cx + 2) * HCELL) - qcx);
        if (cy - 1 > 0)      fy = fminf(fy, qcy - (XMIN + (float)(cy - 1) * HCELL));
        if (cy + 1 < GC - 1) fy = fminf(fy, (XMIN + (float)(cy + 2) * HCELL) - qcy);
        if (cz - 1 > 0)      fz = fminf(fz, qcz - (XMIN + (float)(cz - 1) * HCELL));
        if (cz + 1 < GC - 1) fz = fminf(fz, (XMIN + (float)(cz + 2) * HCELL) - qcz);
        float bnd = fminf(fx, fminf(fy, fz));
        (void)bx;
        done = count_break(bnd * bnd);
    }

    // rings 2..: general walk with box-face break
    for (int r = 2; r <= GC - 1 && !done; ++r) {
        int zlo = max(cz - r, 0), zhi = min(cz + r, GC - 1);
        for (int z = zlo; z <= zhi; ++z) {
            int adz = abs(z - cz);
            int ylo = max(cy - r, 0), yhi = min(cy + r, GC - 1);
            for (int y = ylo; y <= yhi; ++y) {
                bool face = (adz == r) || (abs(y - cy) == r);
                int rb = (z * GC + y) * GC;
                if (face) {
                    int xlo = max(cx - r, 0), xhi = min(cx + r, GC - 1);
                    scan_range(__ldg(&csb[rb + xlo]), __ldg(&csb[rb + xhi + 1]));
                } else {
                    if (cx - r >= 0)
                        scan_range(__ldg(&csb[rb + cx - r]), __ldg(&csb[rb + cx - r + 1]));
                    if (cx + r <= GC - 1)
                        scan_range(__ldg(&csb[rb + cx + r]), __ldg(&csb[rb + cx + r + 1]));
                }
            }
        }
        // box-face bound for the scanned box of radius r
        float fx = 1e30f, fy = 1e30f, fz = 1e30f;
        if (cx - r > 0)      fx = fminf(fx, qcx - (XMIN + (float)(cx - r) * HCELL));
        if (cx + r < GC - 1) fx = fminf(fx, (XMIN + (float)(cx + r + 1) * HCELL) - qcx);
        if (cy - r > 0)      fy = fminf(fy, qcy - (XMIN + (float)(cy - r) * HCELL));
        if (cy + r < GC - 1) fy = fminf(fy, (XMIN + (float)(cy + r + 1) * HCELL) - qcy);
        if (cz - r > 0)      fz = fminf(fz, qcz - (XMIN + (float)(cz - r) * HCELL));
        if (cz + r < GC - 1) fz = fminf(fz, (XMIN + (float)(cz + r + 1) * HCELL) - qcz);
        float bnd = fminf(fx, fminf(fy, fz));
        done = count_break(bnd * bnd);
    }

    // Final exact merge: 11 rounds of warp min-extraction (REDUX.MIN x2).
    int myn = 0;
    {
        ull ck[KP];
        #pragma unroll
        for (int s = 0; s < KP; ++s) ck[s] = hk[s];
        #pragma unroll
        for (int s = 0; s < KP; ++s) {
            unsigned hi  = (unsigned)(ck[0] >> 32);
            unsigned mhi = __reduce_min_sync(FULLM, hi);
            unsigned lo  = (hi == mhi) ? (unsigned)(ck[0] & 0xFFFFFFFFull) : 0xFFFFFFFFu;
            unsigned mlo = __reduce_min_sync(FULLM, lo);
            ull m = ((ull)mhi << 32) | mlo;
            if (lane == s) myn = (int)mlo;
            if (ck[0] == m) {
                #pragma unroll
                for (int t2 = 0; t2 < KP - 1; ++t2) ck[t2] = ck[t2 + 1];
                ck[KP - 1] = SENT;
            }
        }
    }

    // ---- epilogue: lane kk owns neighbor kk; lane 11 owns init features ----
    float acc[6];
    #pragma unroll
    for (int c = 0; c < 6; ++c) acc[c] = 0.f;

    if (lane < KP) {
        const int idx = myn;
        const float* vp = vel + ((size_t)b * NP + idx) * 3;
        float vx = vp[0], vy = vp[1], vz = vp[2];
        const int fv = 30 + lane * 3;
        #pragma unroll
        for (int c = 0; c < 6; ++c)
            acc[c] += Wsh[c * NFEAT + fv + 0] * vx
                    + Wsh[c * NFEAT + fv + 1] * vy
                    + Wsh[c * NFEAT + fv + 2] * vz;
        if (lane >= 1) {
            const float* pp = pos + ((size_t)b * NP + idx) * 3;
            float ox = pp[0] - q.x, oy = pp[1] - q.y, oz = pp[2] - q.z;
            const int fo = (lane - 1) * 3;
            #pragma unroll
            for (int c = 0; c < 6; ++c)
                acc[c] += Wsh[c * NFEAT + fo + 0] * ox
                        + Wsh[c * NFEAT + fo + 1] * oy
                        + Wsh[c * NFEAT + fo + 2] * oz;
        }
    } else if (lane == KP) {
        float i0 = init_cfg[b * 3 + 0];
        float i1 = init_cfg[b * 3 + 1];
        float i2 = init_cfg[b * 3 + 2];
        #pragma unroll
        for (int c = 0; c < 6; ++c)
            acc[c] += Wsh[c * NFEAT + 63] * i0
                    + Wsh[c * NFEAT + 64] * i1
                    + Wsh[c * NFEAT + 65] * i2;
    }
    #pragma unroll
    for (int o = 16; o > 0; o >>= 1) {
        #pragma unroll
        for (int c = 0; c < 6; ++c)
            acc[c] += __shfl_xor_sync(FULLM, acc[c], o);
    }
    if (lane == 0) {
        acc[0] += bsh[0] + q.x;
        acc[1] += bsh[1] + q.y;
        acc[2] += bsh[2] + q.z;
        acc[3] += bsh[3];
        acc[4] += bsh[4];
        acc[5] += bsh[5];
        float* o = out + ((size_t)b * NP + n) * 6;
        #pragma unroll
        for (int c = 0; c < 6; ++c) o[c] = acc[c];
    }
}

extern "C" void kernel_launch(void* const* d_in, const int* in_sizes, int n_in,
                              void* d_out, int out_size) {
    const float* pos      = (const float*)d_in[0];
    const float* vel      = (const float*)d_in[1];
    const float* init_cfg = (const float*)d_in[2];
    const float* W1 = (const float*)d_in[3];
    const float* b1 = (const float*)d_in[4];
    const float* W2 = (const float*)d_in[5];
    const float* b2 = (const float*)d_in[6];
    const float* W3 = (const float*)d_in[7];
    const float* b3 = (const float*)d_in[8];
    float* out = (float*)d_out;

    prep_kernel<<<NB + 1, BT>>>(pos, W1, b1, W2, b2, W3, b3);

    dim3 grid(NP / WPQ, NB);
    search_kernel<<<grid, WPQ * 32>>>(pos, vel, init_cfg, out);
}

// round 17
// speedup vs baseline: 1.3177x; 1.3177x over previous
#include <cuda_runtime.h>

#define NB    4
#define NP    4096
#define KP    11                 // K+1 including self
#define NFEAT 66
#define GC    16                 // grid cells per axis
#define NCELL (GC*GC*GC)         // 4096
#define XMIN  (-4.5f)
#define XMAX  (4.5f)
#define HCELL (9.0f/(float)GC)   // 0.5625
#define IHINV ((float)GC/9.0f)
#define WPQ   8                  // warps (queries) per search block

typedef unsigned long long ull;
#define SENT 0xFFFFFFFFFFFFFFFFull
#define FULLM 0xFFFFFFFFu

__device__ float  g_Weff[6 * NFEAT];
__device__ float  g_beff[6];
__device__ float4 g_spos[NB][NP];          // x,y,z, idx-as-float-bits
__device__ int    g_cs[NB][NCELL + 1];

__device__ __forceinline__ int cell1(float v) {
    int c = (int)(__fmul_rn(__fsub_rn(v, XMIN), IHINV));
    return min(GC - 1, max(0, c));
}
__device__ __forceinline__ unsigned f2ord(float f) {
    unsigned u = __float_as_uint(f);
    return u ^ (((int)u >> 31) | 0x80000000u);
}

// ---------------------------------------------------------------------------
// Fused prep: blocks 0..NB-1 build the per-batch grid; block NB folds weights.
#define BT 512
__global__ void __launch_bounds__(BT)
prep_kernel(const float* __restrict__ pos,
            const float* __restrict__ W1, const float* __restrict__ b1,
            const float* __restrict__ W2, const float* __restrict__ b2,
            const float* __restrict__ W3, const float* __restrict__ b3) {
    __shared__ int hist[NCELL];          // counts -> starts -> cursors
    __shared__ int wsum[BT / 32];
    const int t = threadIdx.x;

    if (blockIdx.x == NB) {
        // ---- fold weights: Weff = W3@W2@W1, beff = W3@(W2@b1+b2)+b3 ----
        __shared__ float sW1[32 * NFEAT];
        __shared__ float sW2[16 * 32];
        __shared__ float sW3[6 * 16];
        __shared__ float sb1[32], sb2[16];
        __shared__ float W32[6 * 32];
        __shared__ float bh[16];
        for (int i = t; i < 32 * NFEAT; i += BT) sW1[i] = W1[i];
        if (t < 512) sW2[t] = W2[t];
        if (t < 96) sW3[t] = W3[t];
        if (t < 32) sb1[t] = b1[t];
        if (t < 16) sb2[t] = b2[t];
        __syncthreads();
        if (t < 192) {
            int c = t >> 5, jj = t & 31;
            float s = 0.f;
            #pragma unroll
            for (int i = 0; i < 16; ++i) s += sW3[c * 16 + i] * sW2[i * 32 + jj];
            W32[c * 32 + jj] = s;
        } else if (t < 208) {
            int i = t - 192;
            float s = sb2[i];
            #pragma unroll
            for (int j = 0; j < 32; ++j) s += sW2[i * 32 + j] * sb1[j];
            bh[i] = s;
        }
        __syncthreads();
        if (t < 396) {
            int c = t / NFEAT, f = t % NFEAT;
            float s = 0.f;
            #pragma unroll
            for (int jj = 0; jj < 32; ++jj) s += W32[c * 32 + jj] * sW1[jj * NFEAT + f];
            g_Weff[c * NFEAT + f] = s;
        } else if (t < 402) {
            int c = t - 396;
            float s = b3[c];
            #pragma unroll
            for (int i = 0; i < 16; ++i) s += sW3[c * 16 + i] * bh[i];
            g_beff[c] = s;
        }
        return;
    }

    // ---- grid build for batch b ----
    const int b = blockIdx.x;
    const int lane = t & 31, w = t >> 5;
    const float* pb = pos + (size_t)b * NP * 3;

    for (int i = t; i < NCELL; i += BT) hist[i] = 0;
    __syncthreads();

    int myc[NP / BT];
    #pragma unroll
    for (int k = 0; k < NP / BT; ++k) {
        int i = t + k * BT;
        float x = pb[3 * i + 0], y = pb[3 * i + 1], z = pb[3 * i + 2];
        int c = (cell1(z) * GC + cell1(y)) * GC + cell1(x);
        myc[k] = c;
        atomicAdd(&hist[c], 1);
    }
    __syncthreads();

    // exclusive scan of NCELL counts: NCELL/BT cells/thread + shuffle scan
    {
        const int base = t * (NCELL / BT);
        int ex[NCELL / BT]; int s = 0;
        #pragma unroll
        for (int k = 0; k < NCELL / BT; ++k) { ex[k] = s; s += hist[base + k]; }
        int v = s;
        #pragma unroll
        for (int off = 1; off < 32; off <<= 1) {
            int u = __shfl_up_sync(FULLM, v, off);
            if (lane >= off) v += u;
        }
        if (lane == 31) wsum[w] = v;
        __syncthreads();
        if (w == 0) {
            int wv = (lane < BT / 32) ? wsum[lane] : 0;
            #pragma unroll
            for (int off = 1; off < 32; off <<= 1) {
                int u = __shfl_up_sync(FULLM, wv, off);
                if (lane >= off) wv += u;
            }
            if (lane < BT / 32) wsum[lane] = wv;
        }
        __syncthreads();
        int woff = (w == 0) ? 0 : wsum[w - 1];
        int tbase = woff + (v - s);
        __syncthreads();                 // reads of hist done before overwrite
        #pragma unroll
        for (int k = 0; k < NCELL / BT; ++k) {
            int st = tbase + ex[k];
            g_cs[b][base + k] = st;
            hist[base + k] = st;         // becomes scatter cursor
        }
        if (t == 0) g_cs[b][NCELL] = NP;
    }
    __syncthreads();

    #pragma unroll
    for (int k = 0; k < NP / BT; ++k) {
        int i = t + k * BT;
        float x = pb[3 * i + 0], y = pb[3 * i + 1], z = pb[3 * i + 2];
        int off = atomicAdd(&hist[myc[k]], 1);
        g_spos[b][off] = make_float4(x, y, z, __int_as_float(i));
    }
}

// ---------------------------------------------------------------------------
// Search: one warp per query. Cell-start table staged in SMEM (kills the
// serial L2-latency chain on bounds fetches). 3x3x3 scanned as 9 full-row
// calls, exact box-face break (capped-count REDUX), then generic ring walk.
// Per-lane sorted top-11 on u64 keys (ord(d2)<<32 | orig_idx); final
// 11-round REDUX min-extract. d2 arithmetic bit-pinned to the reference.
__global__ void __launch_bounds__(WPQ * 32)
search_kernel(const float* __restrict__ pos,
              const float* __restrict__ vel,
              const float* __restrict__ init_cfg,
              float* __restrict__ out) {
    __shared__ int   scs[NCELL + 1];     // 16.4 KB cell starts
    __shared__ float Wsh[6 * NFEAT];
    __shared__ float bsh[8];
    const int tid = threadIdx.x;
    const int b   = blockIdx.y;
    for (int i = tid; i < NCELL + 1; i += WPQ * 32) scs[i] = g_cs[b][i];
    for (int i = tid; i < 6 * NFEAT; i += WPQ * 32) Wsh[i] = g_Weff[i];
    if (tid < 6) bsh[tid] = g_beff[tid];
    __syncthreads();

    const int wid  = tid >> 5;
    const int lane = tid & 31;
    const int s_q  = blockIdx.x * WPQ + wid;      // sorted query index

    const float4 q = g_spos[b][s_q];
    const int    n = __float_as_int(q.w);         // original query index
    const float qsq = __fadd_rn(__fadd_rn(__fmul_rn(q.x, q.x), __fmul_rn(q.y, q.y)),
                                __fmul_rn(q.z, q.z));
    const float qcx = fminf(fmaxf(q.x, XMIN), XMAX);
    const float qcy = fminf(fmaxf(q.y, XMIN), XMAX);
    const float qcz = fminf(fmaxf(q.z, XMIN), XMAX);
    const int cx = cell1(q.x), cy = cell1(q.y), cz = cell1(q.z);
    const float4* sp = g_spos[b];

    ull hk[KP];
    #pragma unroll
    for (int s = 0; s < KP; ++s) hk[s] = SENT;

    auto scan_range = [&](int a, int e) {
        for (int i = a + lane; i < e; i += 32) {
            float4 p = __ldg(&sp[i]);
            float psq = __fadd_rn(__fadd_rn(__fmul_rn(p.x, p.x), __fmul_rn(p.y, p.y)),
                                  __fmul_rn(p.z, p.z));
            float dot = __fmul_rn(q.x, p.x);
            dot = __fmaf_rn(q.y, p.y, dot);
            dot = __fmaf_rn(q.z, p.z, dot);
            float S  = __fadd_rn(qsq, psq);
            float d2 = __fsub_rn(S, __fmul_rn(2.0f, dot));
            ull key = ((ull)f2ord(d2) << 32) | (unsigned)__float_as_int(p.w);
            if (key < hk[KP - 1]) {
                hk[KP - 1] = key;
                #pragma unroll
                for (int s = KP - 1; s > 0; --s) {
                    if (hk[s] < hk[s - 1]) { ull t2 = hk[s - 1]; hk[s - 1] = hk[s]; hk[s] = t2; }
                    else break;
                }
            }
        }
    };

    // capped-count exact test: >= KP union keys strictly below bnd2?
    auto count_break = [&](float bnd2) -> bool {
        if (!(bnd2 > 1e-12f)) return false;
        unsigned bkey = f2ord(__fmul_rn(0.998f, bnd2));
        unsigned cnt = 0;
        #pragma unroll
        for (int s = 0; s < KP; ++s) cnt += ((unsigned)(hk[s] >> 32) < bkey) ? 1u : 0u;
        return __reduce_add_sync(FULLM, cnt) >= KP;
    };

    // box-face bound for the scanned box of radius R (clamped space; grid-edge
    // faces have nothing beyond them -> +inf; clamping is 1-Lipschitz so true
    // distances only exceed clamped ones => bound exact)
    auto box_bound2 = [&](int R) -> float {
        float f = 1e30f;
        if (cx - R > 0)      f = fminf(f, qcx - (XMIN + (float)(cx - R) * HCELL));
        if (cx + R < GC - 1) f = fminf(f, (XMIN + (float)(cx + R + 1) * HCELL) - qcx);
        if (cy - R > 0)      f = fminf(f, qcy - (XMIN + (float)(cy - R) * HCELL));
        if (cy + R < GC - 1) f = fminf(f, (XMIN + (float)(cy + R + 1) * HCELL) - qcy);
        if (cz - R > 0)      f = fminf(f, qcz - (XMIN + (float)(cz - R) * HCELL));
        if (cz + R < GC - 1) f = fminf(f, (XMIN + (float)(cz + R + 1) * HCELL) - qcz);
        if (f > 1e29f) return 1e30f;
        return f * f;
    };

    bool done = false;

    // rings 0..1: the 3x3x3 box as 9 contiguous full-row scans
    {
        const int xlo = max(cx - 1, 0), xhi = min(cx + 1, GC - 1);
        #pragma unroll
        for (int dz = -1; dz <= 1; ++dz) {
            int z = cz + dz; if ((unsigned)z >= GC) continue;
            #pragma unroll
            for (int dy = -1; dy <= 1; ++dy) {
                int y = cy + dy; if ((unsigned)y >= GC) continue;
                int rb = (z * GC + y) * GC;
                scan_range(scs[rb + xlo], scs[rb + xhi + 1]);
            }
        }
        done = count_break(box_bound2(1));
    }

    // rings 2..: general walk
    for (int r = 2; r <= GC - 1 && !done; ++r) {
        int zlo = max(cz - r, 0), zhi = min(cz + r, GC - 1);
        for (int z = zlo; z <= zhi; ++z) {
            int adz = abs(z - cz);
            int ylo = max(cy - r, 0), yhi = min(cy + r, GC - 1);
            for (int y = ylo; y <= yhi; ++y) {
                bool face = (adz == r) || (abs(y - cy) == r);
                int rb = (z * GC + y) * GC;
                if (face) {
                    int xlo = max(cx - r, 0), xhi = min(cx + r, GC - 1);
                    scan_range(scs[rb + xlo], scs[rb + xhi + 1]);
                } else {
                    if (cx - r >= 0)      scan_range(scs[rb + cx - r], scs[rb + cx - r + 1]);
                    if (cx + r <= GC - 1) scan_range(scs[rb + cx + r], scs[rb + cx + r + 1]);
                }
            }
        }
        done = count_break(box_bound2(r));
    }

    // Final exact merge: 11 rounds of warp min-extraction (REDUX.MIN x2).
    int myn = 0;
    {
        ull ck[KP];
        #pragma unroll
        for (int s = 0; s < KP; ++s) ck[s] = hk[s];
        #pragma unroll
        for (int s = 0; s < KP; ++s) {
            unsigned hi  = (unsigned)(ck[0] >> 32);
            unsigned mhi = __reduce_min_sync(FULLM, hi);
            unsigned lo  = (hi == mhi) ? (unsigned)(ck[0] & 0xFFFFFFFFull) : 0xFFFFFFFFu;
            unsigned mlo = __reduce_min_sync(FULLM, lo);
            ull m = ((ull)mhi << 32) | mlo;
            if (lane == s) myn = (int)mlo;
            if (ck[0] == m) {
                #pragma unroll
                for (int t2 = 0; t2 < KP - 1; ++t2) ck[t2] = ck[t2 + 1];
                ck[KP - 1] = SENT;
            }
        }
    }

    // ---- epilogue: lane kk owns neighbor kk; lane 11 owns init features ----
    float acc[6];
    #pragma unroll
    for (int c = 0; c < 6; ++c) acc[c] = 0.f;

    if (lane < KP) {
        const int idx = myn;
        const float* vp = vel + ((size_t)b * NP + idx) * 3;
        float vx = vp[0], vy = vp[1], vz = vp[2];
        const int fv = 30 + lane * 3;
        #pragma unroll
        for (int c = 0; c < 6; ++c)
            acc[c] += Wsh[c * NFEAT + fv + 0] * vx
                    + Wsh[c * NFEAT + fv + 1] * vy
                    + Wsh[c * NFEAT + fv + 2] * vz;
        if (lane >= 1) {
            const float* pp = pos + ((size_t)b * NP + idx) * 3;
            float ox = pp[0] - q.x, oy = pp[1] - q.y, oz = pp[2] - q.z;
            const int fo = (lane - 1) * 3;
            #pragma unroll
            for (int c = 0; c < 6; ++c)
                acc[c] += Wsh[c * NFEAT + fo + 0] * ox
                        + Wsh[c * NFEAT + fo + 1] * oy
                        + Wsh[c * NFEAT + fo + 2] * oz;
        }
    } else if (lane == KP) {
        float i0 = init_cfg[b * 3 + 0];
        float i1 = init_cfg[b * 3 + 1];
        float i2 = init_cfg[b * 3 + 2];
        #pragma unroll
        for (int c = 0; c < 6; ++c)
            acc[c] += Wsh[c * NFEAT + 63] * i0
                    + Wsh[c * NFEAT + 64] * i1
                    + Wsh[c * NFEAT + 65] * i2;
    }
    #pragma unroll
    for (int o = 16; o > 0; o >>= 1) {
        #pragma unroll
        for (int c = 0; c < 6; ++c)
            acc[c] += __shfl_xor_sync(FULLM, acc[c], o);
    }
    if (lane == 0) {
        acc[0] += bsh[0] + q.x;
        acc[1] += bsh[1] + q.y;
        acc[2] += bsh[2] + q.z;
        acc[3] += bsh[3];
        acc[4] += bsh[4];
        acc[5] += bsh[5];
        float* o = out + ((size_t)b * NP + n) * 6;
        #pragma unroll
        for (int c = 0; c < 6; ++c) o[c] = acc[c];
    }
}

extern "C" void kernel_launch(void* const* d_in, const int* in_sizes, int n_in,
                              void* d_out, int out_size) {
    const float* pos      = (const float*)d_in[0];
    const float* vel      = (const float*)d_in[1];
    const float* init_cfg = (const float*)d_in[2];
    const float* W1 = (const float*)d_in[3];
    const float* b1 = (const float*)d_in[4];
    const float* W2 = (const float*)d_in[5];
    const float* b2 = (const float*)d_in[6];
    const float* W3 = (const float*)d_in[7];
    const float* b3 = (const float*)d_in[8];
    float* out = (float*)d_out;

    prep_kernel<<<NB + 1, BT>>>(pos, W1, b1, W2, b2, W3, b3);

    dim3 grid(NP / WPQ, NB);
    search_kernel<<<grid, WPQ * 32>>>(pos, vel, init_cfg, out);
}